// round 2
// baseline (speedup 1.0000x reference)
#include <cuda_runtime.h>
#include <math.h>

#define NN 50000
#define NE 800000
#define CC 64
#define HH 8

// ---------------- scratch (device globals; no allocation allowed) ----------------
__device__ float g_f0[NN * 64];            // node scalar features
__device__ float g_f1[NN * 192];           // node vector features (C,3)
__device__ float g_agg0[NN * 64];
__device__ float g_agg1[NN * 192];
__device__ float g_z[NN * 8];
__device__ unsigned int g_amax[NN * 8];    // encoded-float max
__device__ float g_wattn[256000000];       // E*320
__device__ float g_msg0[51200000];         // E*64
__device__ float g_msg1[153600000];        // E*192
__device__ float g_a[6400000];             // E*8

// ---------------- helpers ----------------
__device__ __forceinline__ float siluf(float x) { return x / (1.f + expf(-x)); }
__device__ __forceinline__ float sigf(float x) { return 1.f / (1.f + expf(-x)); }

// order-preserving float<->uint encoding for atomicMax on floats
__device__ __forceinline__ unsigned int encf(float f) {
    unsigned int u = __float_as_uint(f);
    return (u & 0x80000000u) ? ~u : (u | 0x80000000u);
}
__device__ __forceinline__ float decf(unsigned int u) {
    return (u & 0x80000000u) ? __uint_as_float(u ^ 0x80000000u) : __uint_as_float(~u);
}

// ---------------- K0: init node state ----------------
__global__ void k0_init(const float* __restrict__ embed_W, const int* __restrict__ node_atom) {
    int stride = gridDim.x * blockDim.x;
    for (int i = blockIdx.x * blockDim.x + threadIdx.x; i < NN * 192; i += stride) {
        g_f1[i] = 0.f;
        g_agg1[i] = 0.f;
        if (i < NN * 64) {
            int n = i >> 6, c = i & 63;
            g_f0[i] = embed_W[node_atom[n] * 64 + c];
            g_agg0[i] = 0.f;
        }
        if (i < NN * 8) {
            g_amax[i] = 0x007FFFFFu;  // enc(-inf)
            g_z[i] = 0.f;
        }
    }
}

// ---------------- K1: per-edge radial MLP + degree scatter ----------------
__global__ void __launch_bounds__(256) k1_edge(
    const float* __restrict__ pos, const float* __restrict__ exp_w,
    const float* __restrict__ W1, const float* __restrict__ b1,
    const float* __restrict__ W2, const float* __restrict__ b2,
    const float* __restrict__ Wdeg, const float* __restrict__ bdeg,
    const float* __restrict__ Wattn, const float* __restrict__ battn,
    const float* __restrict__ P0, const float* __restrict__ P1,
    const int* __restrict__ esrc, const int* __restrict__ edst)
{
    __shared__ float sm[8][256];  // per-warp: [0:64) rbf, [64:128) h, [128:192) e0, [192:256) g
    int warp = threadIdx.x >> 5, lane = threadIdx.x & 31;
    int e = blockIdx.x * 8 + warp;
    if (e >= NE) return;
    float* srbf = sm[warp];
    float* sh   = sm[warp] + 64;
    float* se0  = sm[warp] + 128;
    float* sg   = sm[warp] + 192;

    int s = esrc[e], d = edst[e];
    float vx = pos[d * 3 + 0] - pos[s * 3 + 0];
    float vy = pos[d * 3 + 1] - pos[s * 3 + 1];
    float vz = pos[d * 3 + 2] - pos[s * 3 + 2];
    float dist = sqrtf(vx * vx + vy * vy + vz * vz + 1e-9f);
    float ri = 1.f / dist;
    float y0 = vx * ri, y1 = vy * ri, y2 = vz * ri;

    // RBF
    const float START = 0.006737946999085467f;          // exp(-5)
    const float STEP  = (1.0f - START) / 49.0f;
    const float BETA  = 1.0f / ((0.04f * (1.0f - START)) * (0.04f * (1.0f - START)));
    const float PI_   = 3.14159265358979323846f;
    float cut = (dist < 5.0f) ? 0.5f * (cosf(PI_ * dist * 0.2f) + 1.f) : 0.f;
    float expd = expf(-dist);  // alpha_s = 1
    for (int k = lane; k < 50; k += 32) {
        float t = expd - (START + (float)k * STEP);
        srbf[k] = cut * expf(-BETA * t * t);
    }
    __syncwarp();

    // layer 1: 50 -> 64
    float h0 = b1[lane], h1 = b1[lane + 32];
#pragma unroll 5
    for (int k = 0; k < 50; k++) {
        float r = srbf[k];
        h0 += r * W1[k * 64 + lane];
        h1 += r * W1[k * 64 + lane + 32];
    }
    h0 = siluf(h0); h1 = siluf(h1);
    sh[lane] = h0; sh[lane + 32] = h1;
    __syncwarp();

    // layer 2: 64 -> 64
    float q0 = b2[lane], q1 = b2[lane + 32];
#pragma unroll 8
    for (int k = 0; k < 64; k++) {
        float r = sh[k];
        q0 += r * W2[k * 64 + lane];
        q1 += r * W2[k * 64 + lane + 32];
    }
    q0 = siluf(q0); q1 = siluf(q1);
    __syncwarp();
    sh[lane] = q0; sh[lane + 32] = q1;
    __syncwarp();

    // w_deg: 64 -> 128
    float wd[4];
#pragma unroll
    for (int m = 0; m < 4; m++) wd[m] = bdeg[lane + 32 * m];
#pragma unroll 8
    for (int k = 0; k < 64; k++) {
        float r = sh[k];
#pragma unroll
        for (int m = 0; m < 4; m++) wd[m] += r * Wdeg[k * 128 + lane + 32 * m];
    }
    se0[lane]      = wd[0] * exp_w[lane];
    se0[lane + 32] = wd[1] * exp_w[lane + 32];
    sg[lane]       = wd[2] * exp_w[lane];
    sg[lane + 32]  = wd[3] * exp_w[lane + 32];
    __syncwarp();

    // degree projections + scatter
    float t0a = 0.f, t0b = 0.f, t1a = 0.f, t1b = 0.f;
#pragma unroll 8
    for (int c = 0; c < 64; c++) {
        float a0 = se0[c], a1 = sg[c];
        t0a += a0 * P0[c * 64 + lane];
        t0b += a0 * P0[c * 64 + lane + 32];
        t1a += a1 * P1[c * 64 + lane];
        t1b += a1 * P1[c * 64 + lane + 32];
    }
    const float INV = 0.25f;  // 1/sqrt(16)
    atomicAdd(&g_f0[d * 64 + lane],      INV * t0a);
    atomicAdd(&g_f0[d * 64 + lane + 32], INV * t0b);
    float u1a = INV * t1a, u1b = INV * t1b;
    atomicAdd(&g_f1[d * 192 + lane * 3 + 0], u1a * y0);
    atomicAdd(&g_f1[d * 192 + lane * 3 + 1], u1a * y1);
    atomicAdd(&g_f1[d * 192 + lane * 3 + 2], u1a * y2);
    atomicAdd(&g_f1[d * 192 + (lane + 32) * 3 + 0], u1b * y0);
    atomicAdd(&g_f1[d * 192 + (lane + 32) * 3 + 1], u1b * y1);
    atomicAdd(&g_f1[d * 192 + (lane + 32) * 3 + 2], u1b * y2);

    // w_attn: 64 -> 320, store for pass 2
    float wa[10];
#pragma unroll
    for (int m = 0; m < 10; m++) wa[m] = battn[lane + 32 * m];
#pragma unroll 4
    for (int k = 0; k < 64; k++) {
        float r = sh[k];
#pragma unroll
        for (int m = 0; m < 10; m++) wa[m] += r * Wattn[k * 320 + lane + 32 * m];
    }
    long long wb = (long long)e * 320;
#pragma unroll
    for (int m = 0; m < 10; m++) g_wattn[wb + lane + 32 * m] = wa[m];
}

// ---------------- K2: messages + logits + segment max ----------------
__global__ void __launch_bounds__(256) k2_msg(
    const float* __restrict__ pos, const float* __restrict__ alpha_dot,
    const int* __restrict__ esrc, const int* __restrict__ edst)
{
    int warp = threadIdx.x >> 5, lane = threadIdx.x & 31;
    int e = blockIdx.x * 8 + warp;
    if (e >= NE) return;
    int s = esrc[e], d = edst[e];
    float vx = pos[d * 3 + 0] - pos[s * 3 + 0];
    float vy = pos[d * 3 + 1] - pos[s * 3 + 1];
    float vz = pos[d * 3 + 2] - pos[s * 3 + 2];
    float dist = sqrtf(vx * vx + vy * vy + vz * vz + 1e-9f);
    float ri = 1.f / dist;
    float y0 = vx * ri, y1 = vy * ri, y2 = vz * ri;

    int c0 = lane, c1 = lane + 32;
    float s0a = g_f0[s * 64 + c0], s0b = g_f0[s * 64 + c1];
    const float* f1p = &g_f1[s * 192];
    float sa0 = f1p[c0 * 3], sa1 = f1p[c0 * 3 + 1], sa2 = f1p[c0 * 3 + 2];
    float sb0 = f1p[c1 * 3], sb1 = f1p[c1 * 3 + 1], sb2 = f1p[c1 * 3 + 2];

    long long wb = (long long)e * 320;
    float w0a = g_wattn[wb + c0],       w0b = g_wattn[wb + c1];
    float w1a = g_wattn[wb + 64 + c0],  w1b = g_wattn[wb + 64 + c1];
    float w2a = g_wattn[wb + 128 + c0], w2b = g_wattn[wb + 128 + c1];
    float w3a = g_wattn[wb + 192 + c0], w3b = g_wattn[wb + 192 + c1];
    float w4a = g_wattn[wb + 256 + c0], w4b = g_wattn[wb + 256 + c1];

    const float IS3 = 0.57735026918962576f;  // 1/sqrt(3)
    const float IS2 = 0.70710678118654752f;  // 1/sqrt(2)

    float dva = sa0 * y0 + sa1 * y1 + sa2 * y2;
    float dvb = sb0 * y0 + sb1 * y1 + sb2 * y2;
    float m0a = w0a * s0a + w3a * dva * IS3;
    float m0b = w0b * s0b + w3b * dvb * IS3;

    float cxa0 = sa1 * y2 - sa2 * y1, cxa1 = sa2 * y0 - sa0 * y2, cxa2 = sa0 * y1 - sa1 * y0;
    float cxb0 = sb1 * y2 - sb2 * y1, cxb1 = sb2 * y0 - sb0 * y2, cxb2 = sb0 * y1 - sb1 * y0;
    float w1sa = w1a * s0a, w1sb = w1b * s0b;
    float m1a0 = w1sa * y0 + w2a * sa0 + w4a * cxa0 * IS2;
    float m1a1 = w1sa * y1 + w2a * sa1 + w4a * cxa1 * IS2;
    float m1a2 = w1sa * y2 + w2a * sa2 + w4a * cxa2 * IS2;
    float m1b0 = w1sb * y0 + w2b * sb0 + w4b * cxb0 * IS2;
    float m1b1 = w1sb * y1 + w2b * sb1 + w4b * cxb1 * IS2;
    float m1b2 = w1sb * y2 + w2b * sb2 + w4b * cxb2 * IS2;

    long long mb0 = (long long)e * 64, mb1 = (long long)e * 192;
    g_msg0[mb0 + c0] = m0a; g_msg0[mb0 + c1] = m0b;
    g_msg1[mb1 + c0 * 3 + 0] = m1a0; g_msg1[mb1 + c0 * 3 + 1] = m1a1; g_msg1[mb1 + c0 * 3 + 2] = m1a2;
    g_msg1[mb1 + c1 * 3 + 0] = m1b0; g_msg1[mb1 + c1 * 3 + 1] = m1b1; g_msg1[mb1 + c1 * 3 + 2] = m1b2;

    float slra = 0.2f * m0a + 0.8f * m0a * sigf(m0a);
    float slrb = 0.2f * m0b + 0.8f * m0b * sigf(m0b);
    float pa = slra * alpha_dot[c0];
    float pb = slrb * alpha_dot[c1];
#pragma unroll
    for (int off = 4; off; off >>= 1) {
        pa += __shfl_xor_sync(0xffffffffu, pa, off);
        pb += __shfl_xor_sync(0xffffffffu, pb, off);
    }
    if ((lane & 7) == 0) {
        int h0 = lane >> 3;
        g_a[(long long)e * 8 + h0] = pa;
        g_a[(long long)e * 8 + h0 + 4] = pb;
        atomicMax(&g_amax[d * 8 + h0], encf(pa));
        atomicMax(&g_amax[d * 8 + h0 + 4], encf(pb));
    }
}

// ---------------- K3: exp + fused (z, ea*msg) scatter ----------------
__global__ void __launch_bounds__(256) k3_agg(const int* __restrict__ edst) {
    int warp = threadIdx.x >> 5, lane = threadIdx.x & 31;
    int e = blockIdx.x * 8 + warp;
    if (e >= NE) return;
    int d = edst[e];
    int h0 = lane >> 3, h1 = 4 + (lane >> 3);
    float aa = g_a[(long long)e * 8 + h0];
    float ab = g_a[(long long)e * 8 + h1];
    float ma = decf(g_amax[d * 8 + h0]);
    float mb = decf(g_amax[d * 8 + h1]);
    float eaa = expf(aa - ma), eab = expf(ab - mb);
    if ((lane & 7) == 0) {
        atomicAdd(&g_z[d * 8 + h0], eaa);
        atomicAdd(&g_z[d * 8 + h1], eab);
    }
    long long mb0 = (long long)e * 64, mb1 = (long long)e * 192;
    int c0 = lane, c1 = lane + 32;
    atomicAdd(&g_agg0[d * 64 + c0], eaa * g_msg0[mb0 + c0]);
    atomicAdd(&g_agg0[d * 64 + c1], eab * g_msg0[mb0 + c1]);
#pragma unroll
    for (int i = 0; i < 3; i++) {
        atomicAdd(&g_agg1[d * 192 + c0 * 3 + i], eaa * g_msg1[mb1 + c0 * 3 + i]);
        atomicAdd(&g_agg1[d * 192 + c1 * 3 + i], eab * g_msg1[mb1 + c1 * 3 + i]);
    }
}

// ---------------- K4: node update: out-proj + FFN + write output ----------------
__global__ void __launch_bounds__(256) k4_node(
    const float* __restrict__ P0, const float* __restrict__ P1,
    const float* __restrict__ W1s, const float* __restrict__ b1s,
    const float* __restrict__ W1v, const float* __restrict__ W2s,
    const float* __restrict__ b2s, const float* __restrict__ W2v,
    float* __restrict__ out)
{
    __shared__ float sm[8][832];
    int warp = threadIdx.x >> 5, lane = threadIdx.x & 31;
    int n = blockIdx.x * 8 + warp;
    if (n >= NN) return;
    float* sA0 = sm[warp];         // 64
    float* sA1 = sm[warp] + 64;    // 192
    float* sF0 = sm[warp] + 256;   // 64
    float* sF1 = sm[warp] + 320;   // 192
    float* sMS = sm[warp] + 512;   // 64
    float* sG  = sm[warp] + 576;   // 64
    float* sMV = sm[warp] + 640;   // 192

    int c0 = lane, c1 = lane + 32;
    float za = g_z[n * 8 + (lane >> 3)];
    float zb = g_z[n * 8 + 4 + (lane >> 3)];
    float rza = za > 0.f ? 1.f / za : 0.f;
    float rzb = zb > 0.f ? 1.f / zb : 0.f;
    sA0[c0] = g_agg0[n * 64 + c0] * rza;
    sA0[c1] = g_agg0[n * 64 + c1] * rzb;
#pragma unroll
    for (int i = 0; i < 3; i++) {
        sA1[c0 * 3 + i] = g_agg1[n * 192 + c0 * 3 + i] * rza;
        sA1[c1 * 3 + i] = g_agg1[n * 192 + c1 * 3 + i] * rzb;
    }
    sF0[c0] = g_f0[n * 64 + c0];
    sF0[c1] = g_f0[n * 64 + c1];
#pragma unroll
    for (int i = 0; i < 3; i++) {
        sF1[c0 * 3 + i] = g_f1[n * 192 + c0 * 3 + i];
        sF1[c1 * 3 + i] = g_f1[n * 192 + c1 * 3 + i];
    }
    __syncwarp();

    // out projections
    float f0a = sF0[c0], f0b = sF0[c1];
    float f1a[3] = {sF1[c0 * 3], sF1[c0 * 3 + 1], sF1[c0 * 3 + 2]};
    float f1b[3] = {sF1[c1 * 3], sF1[c1 * 3 + 1], sF1[c1 * 3 + 2]};
#pragma unroll 4
    for (int c = 0; c < 64; c++) {
        float r = sA0[c];
        f0a += r * P0[c * 64 + c0];
        f0b += r * P0[c * 64 + c1];
        float wa = P1[c * 64 + c0], wbv = P1[c * 64 + c1];
#pragma unroll
        for (int i = 0; i < 3; i++) {
            f1a[i] += sA1[c * 3 + i] * wa;
            f1b[i] += sA1[c * 3 + i] * wbv;
        }
    }
    __syncwarp();
    sF0[c0] = f0a; sF0[c1] = f0b;
#pragma unroll
    for (int i = 0; i < 3; i++) { sF1[c0 * 3 + i] = f1a[i]; sF1[c1 * 3 + i] = f1b[i]; }
    __syncwarp();

    // FFN layer 1 (scalar + gate)
    float hs0 = b1s[c0], hs1 = b1s[c1], hs2 = b1s[64 + c0], hs3 = b1s[64 + c1];
#pragma unroll 4
    for (int c = 0; c < 64; c++) {
        float r = sF0[c];
        hs0 += r * W1s[c * 128 + c0];
        hs1 += r * W1s[c * 128 + c1];
        hs2 += r * W1s[c * 128 + 64 + c0];
        hs3 += r * W1s[c * 128 + 64 + c1];
    }
    sMS[c0] = siluf(hs0); sMS[c1] = siluf(hs1);
    sG[c0] = sigf(hs2);   sG[c1] = sigf(hs3);
    __syncwarp();

    // vector branch
    float mva[3] = {0, 0, 0}, mvb[3] = {0, 0, 0};
#pragma unroll 4
    for (int c = 0; c < 64; c++) {
        float wa = W1v[c * 64 + c0], wbv = W1v[c * 64 + c1];
#pragma unroll
        for (int i = 0; i < 3; i++) {
            mva[i] += sF1[c * 3 + i] * wa;
            mvb[i] += sF1[c * 3 + i] * wbv;
        }
    }
    float ga = sG[c0], gb = sG[c1];
#pragma unroll
    for (int i = 0; i < 3; i++) { sMV[c0 * 3 + i] = mva[i] * ga; sMV[c1 * 3 + i] = mvb[i] * gb; }
    __syncwarp();

    // FFN layer 2 + residuals
    float o0a = sF0[c0] + b2s[c0], o0b = sF0[c1] + b2s[c1];
    float o1a[3] = {sF1[c0 * 3], sF1[c0 * 3 + 1], sF1[c0 * 3 + 2]};
    float o1b[3] = {sF1[c1 * 3], sF1[c1 * 3 + 1], sF1[c1 * 3 + 2]};
#pragma unroll 4
    for (int c = 0; c < 64; c++) {
        float r = sMS[c];
        o0a += r * W2s[c * 64 + c0];
        o0b += r * W2s[c * 64 + c1];
        float wa = W2v[c * 64 + c0], wbv = W2v[c * 64 + c1];
#pragma unroll
        for (int i = 0; i < 3; i++) {
            o1a[i] += sMV[c * 3 + i] * wa;
            o1b[i] += sMV[c * 3 + i] * wbv;
        }
    }

    long long ob = (long long)n * 256;
    out[ob + c0] = o0a;
    out[ob + c1] = o0b;
#pragma unroll
    for (int i = 0; i < 3; i++) {
        out[ob + 64 + c0 * 3 + i] = o1a[i];
        out[ob + 64 + c1 * 3 + i] = o1b[i];
    }
}

// ---------------- launch ----------------
extern "C" void kernel_launch(void* const* d_in, const int* in_sizes, int n_in,
                              void* d_out, int out_size) {
    const float* pos       = (const float*)d_in[0];
    const float* embed_W   = (const float*)d_in[1];
    const float* exp_w     = (const float*)d_in[2];
    const float* rad_W1    = (const float*)d_in[3];
    const float* rad_b1    = (const float*)d_in[4];
    const float* rad_W2    = (const float*)d_in[5];
    const float* rad_b2    = (const float*)d_in[6];
    const float* rad_Wdeg  = (const float*)d_in[7];
    const float* rad_bdeg  = (const float*)d_in[8];
    const float* rad_Wattn = (const float*)d_in[9];
    const float* rad_battn = (const float*)d_in[10];
    const float* deg_proj0 = (const float*)d_in[11];
    const float* deg_proj1 = (const float*)d_in[12];
    const float* alpha_dot = (const float*)d_in[13];
    const float* out_proj0 = (const float*)d_in[14];
    const float* out_proj1 = (const float*)d_in[15];
    const float* ffn_W1s   = (const float*)d_in[16];
    const float* ffn_b1s   = (const float*)d_in[17];
    const float* ffn_W1v   = (const float*)d_in[18];
    const float* ffn_W2s   = (const float*)d_in[19];
    const float* ffn_b2s   = (const float*)d_in[20];
    const float* ffn_W2v   = (const float*)d_in[21];
    const int* node_atom   = (const int*)d_in[22];
    const int* edge_src    = (const int*)d_in[23];
    const int* edge_dst    = (const int*)d_in[24];
    float* out = (float*)d_out;

    k0_init<<<1024, 256>>>(embed_W, node_atom);
    k1_edge<<<NE / 8, 256>>>(pos, exp_w, rad_W1, rad_b1, rad_W2, rad_b2,
                             rad_Wdeg, rad_bdeg, rad_Wattn, rad_battn,
                             deg_proj0, deg_proj1, edge_src, edge_dst);
    k2_msg<<<NE / 8, 256>>>(pos, alpha_dot, edge_src, edge_dst);
    k3_agg<<<NE / 8, 256>>>(edge_dst);
    k4_node<<<NN / 8, 256>>>(out_proj0, out_proj1, ffn_W1s, ffn_b1s,
                             ffn_W1v, ffn_W2s, ffn_b2s, ffn_W2v, out);
}

// round 3
// speedup vs baseline: 1.9960x; 1.9960x over previous
#include <cuda_runtime.h>
#include <cuda_fp16.h>
#include <math.h>

#define NN 50000
#define NE 800000

// ---------------- scratch (device globals; no allocation allowed) ----------------
__device__ float g_f0[NN * 64];            // node scalar features
__device__ float g_f1[NN * 192];           // node vector features (C,3)
__device__ float g_agg0[NN * 64];
__device__ float g_agg1[NN * 192];
__device__ float g_z[NN * 8];
__device__ unsigned int g_amax[NN * 8];    // encoded-float max
__device__ __half g_wattn_h[256000000];    // E*320 (fp16)
__device__ __half g_msg0_h[51200000];      // E*64  (fp16)
__device__ __half g_msg1_h[153600000];     // E*192 (fp16, layout [e][comp][64])
__device__ float g_a[6400000];             // E*8

// ---------------- helpers ----------------
__device__ __forceinline__ float siluf(float x) { return x / (1.f + expf(-x)); }
__device__ __forceinline__ float sigf(float x) { return 1.f / (1.f + expf(-x)); }

__device__ __forceinline__ unsigned int encf(float f) {
    unsigned int u = __float_as_uint(f);
    return (u & 0x80000000u) ? ~u : (u | 0x80000000u);
}
__device__ __forceinline__ float decf(unsigned int u) {
    return (u & 0x80000000u) ? __uint_as_float(u ^ 0x80000000u) : __uint_as_float(~u);
}

// ---------------- K0: init node state ----------------
__global__ void k0_init(const float* __restrict__ embed_W, const int* __restrict__ node_atom) {
    int stride = gridDim.x * blockDim.x;
    for (int i = blockIdx.x * blockDim.x + threadIdx.x; i < NN * 192; i += stride) {
        g_f1[i] = 0.f;
        g_agg1[i] = 0.f;
        if (i < NN * 64) {
            int n = i >> 6, c = i & 63;
            g_f0[i] = embed_W[node_atom[n] * 64 + c];
            g_agg0[i] = 0.f;
        }
        if (i < NN * 8) {
            g_amax[i] = 0x007FFFFFu;  // enc(-inf)
            g_z[i] = 0.f;
        }
    }
}

// ---------------- tiled GEMM core: 64 edges x 4x4 register tile per thread ----------
// As: smem activations [64 edges][64] (stride 64). Bg: global weights row-major [K][ldb].
// Each thread: edges eA..eA+3, cols colbase+cg*4..+3.
__device__ __forceinline__ void gemm_acc(const float* __restrict__ As, int eA,
                                         const float* __restrict__ Bg, int ldb,
                                         int colbase, int cg, int K,
                                         float acc[4][4]) {
#pragma unroll
    for (int i = 0; i < 4; i++)
#pragma unroll
        for (int j = 0; j < 4; j++) acc[i][j] = 0.f;
    const float* Bp = Bg + colbase + (cg << 2);
    const float* A0 = As + (eA + 0) * 64;
    const float* A1 = As + (eA + 1) * 64;
    const float* A2 = As + (eA + 2) * 64;
    const float* A3 = As + (eA + 3) * 64;
#pragma unroll 4
    for (int k = 0; k < K; k++) {
        float4 b = *reinterpret_cast<const float4*>(Bp + k * ldb);
        float a0 = A0[k], a1 = A1[k], a2 = A2[k], a3 = A3[k];
        acc[0][0] += a0 * b.x; acc[0][1] += a0 * b.y; acc[0][2] += a0 * b.z; acc[0][3] += a0 * b.w;
        acc[1][0] += a1 * b.x; acc[1][1] += a1 * b.y; acc[1][2] += a1 * b.z; acc[1][3] += a1 * b.w;
        acc[2][0] += a2 * b.x; acc[2][1] += a2 * b.y; acc[2][2] += a2 * b.z; acc[2][3] += a2 * b.w;
        acc[3][0] += a3 * b.x; acc[3][1] += a3 * b.y; acc[3][2] += a3 * b.z; acc[3][3] += a3 * b.w;
    }
}

// ---------------- K1: edge-tiled radial MLP (GEMM) + degree scatter + w_attn ------
__global__ void __launch_bounds__(256) k1_edge(
    const float* __restrict__ pos, const float* __restrict__ exp_w,
    const float* __restrict__ W1, const float* __restrict__ b1,
    const float* __restrict__ W2, const float* __restrict__ b2,
    const float* __restrict__ Wdeg, const float* __restrict__ bdeg,
    const float* __restrict__ Wattn, const float* __restrict__ battn,
    const float* __restrict__ P0, const float* __restrict__ P1,
    const int* __restrict__ esrc, const int* __restrict__ edst)
{
    __shared__ float SA[64 * 64];
    __shared__ float SB[64 * 64];
    __shared__ float SC[64 * 64];

    int tid = threadIdx.x;
    int cg = tid & 15;          // column group (4 cols)
    int eA = (tid >> 4) << 2;   // first edge of this thread's 4-edge group
    int ebase = blockIdx.x * 64;

    // --- geometry: threads 0..63, one edge each; stash cut/expd in SB ---
    if (tid < 64) {
        int e = ebase + tid;
        int s = esrc[e], d = edst[e];
        float vx = pos[d * 3 + 0] - pos[s * 3 + 0];
        float vy = pos[d * 3 + 1] - pos[s * 3 + 1];
        float vz = pos[d * 3 + 2] - pos[s * 3 + 2];
        float dist = sqrtf(vx * vx + vy * vy + vz * vz + 1e-9f);
        const float PI_ = 3.14159265358979323846f;
        float cut = (dist < 5.0f) ? 0.5f * (cosf(PI_ * dist * 0.2f) + 1.f) : 0.f;
        SB[tid] = cut;
        SB[64 + tid] = expf(-dist);
    }
    __syncthreads();

    // --- RBF: SA[e][k], k<50 ---
    {
        const float START = 0.006737946999085467f;
        const float STEP = (1.0f - START) / 49.0f;
        const float BETA = 1.0f / ((0.04f * (1.0f - START)) * (0.04f * (1.0f - START)));
        int er = tid & 63, krow = tid >> 6;
        float cut = SB[er], expd = SB[64 + er];
        for (int k = krow; k < 50; k += 4) {
            float t = expd - (START + (float)k * STEP);
            SA[er * 64 + k] = cut * expf(-BETA * t * t);
        }
    }
    __syncthreads();

    float acc[4][4];
    int c4 = cg << 2;

    // --- GEMM1: rbf(50) -> 64, silu -> SB ---
    gemm_acc(SA, eA, W1, 64, 0, cg, 50, acc);
    {
        float bx = b1[c4], by = b1[c4 + 1], bz = b1[c4 + 2], bw = b1[c4 + 3];
#pragma unroll
        for (int i = 0; i < 4; i++) {
            float4 o;
            o.x = siluf(acc[i][0] + bx);
            o.y = siluf(acc[i][1] + by);
            o.z = siluf(acc[i][2] + bz);
            o.w = siluf(acc[i][3] + bw);
            *reinterpret_cast<float4*>(&SB[(eA + i) * 64 + c4]) = o;
        }
    }
    __syncthreads();

    // --- GEMM2: 64 -> 64, silu -> SC ---
    gemm_acc(SB, eA, W2, 64, 0, cg, 64, acc);
    {
        float bx = b2[c4], by = b2[c4 + 1], bz = b2[c4 + 2], bw = b2[c4 + 3];
#pragma unroll
        for (int i = 0; i < 4; i++) {
            float4 o;
            o.x = siluf(acc[i][0] + bx);
            o.y = siluf(acc[i][1] + by);
            o.z = siluf(acc[i][2] + bz);
            o.w = siluf(acc[i][3] + bw);
            *reinterpret_cast<float4*>(&SC[(eA + i) * 64 + c4]) = o;
        }
    }
    __syncthreads();

    // --- GEMM3 chunk0: wd0 -> e0 = wd0*exp_w -> SA ---
    gemm_acc(SC, eA, Wdeg, 128, 0, cg, 64, acc);
    {
        float bx = bdeg[c4], by = bdeg[c4 + 1], bz = bdeg[c4 + 2], bw = bdeg[c4 + 3];
        float ex = exp_w[c4], ey = exp_w[c4 + 1], ez = exp_w[c4 + 2], ew = exp_w[c4 + 3];
#pragma unroll
        for (int i = 0; i < 4; i++) {
            float4 o;
            o.x = (acc[i][0] + bx) * ex;
            o.y = (acc[i][1] + by) * ey;
            o.z = (acc[i][2] + bz) * ez;
            o.w = (acc[i][3] + bw) * ew;
            *reinterpret_cast<float4*>(&SA[(eA + i) * 64 + c4]) = o;
        }
    }
    // --- GEMM3 chunk1: wd1 -> e1 scalar -> SB ---
    gemm_acc(SC, eA, Wdeg, 128, 64, cg, 64, acc);
    {
        float bx = bdeg[64 + c4], by = bdeg[64 + c4 + 1], bz = bdeg[64 + c4 + 2], bw = bdeg[64 + c4 + 3];
        float ex = exp_w[c4], ey = exp_w[c4 + 1], ez = exp_w[c4 + 2], ew = exp_w[c4 + 3];
#pragma unroll
        for (int i = 0; i < 4; i++) {
            float4 o;
            o.x = (acc[i][0] + bx) * ex;
            o.y = (acc[i][1] + by) * ey;
            o.z = (acc[i][2] + bz) * ez;
            o.w = (acc[i][3] + bw) * ew;
            *reinterpret_cast<float4*>(&SB[(eA + i) * 64 + c4]) = o;
        }
    }
    __syncthreads();

    const float INV = 0.25f;  // 1/sqrt(AVG_DEG)

    // --- GEMM4a: e0 @ P0 -> atomic scatter to f0 ---
    gemm_acc(SA, eA, P0, 64, 0, cg, 64, acc);
#pragma unroll
    for (int i = 0; i < 4; i++) {
        int d = edst[ebase + eA + i];
        float* p = &g_f0[d * 64 + c4];
        atomicAdd(p + 0, INV * acc[i][0]);
        atomicAdd(p + 1, INV * acc[i][1]);
        atomicAdd(p + 2, INV * acc[i][2]);
        atomicAdd(p + 3, INV * acc[i][3]);
    }

    // --- GEMM4b: e1 @ P1, times Y -> atomic scatter to f1 ---
    gemm_acc(SB, eA, P1, 64, 0, cg, 64, acc);
#pragma unroll
    for (int i = 0; i < 4; i++) {
        int e = ebase + eA + i;
        int s = esrc[e], d = edst[e];
        float vx = pos[d * 3 + 0] - pos[s * 3 + 0];
        float vy = pos[d * 3 + 1] - pos[s * 3 + 1];
        float vz = pos[d * 3 + 2] - pos[s * 3 + 2];
        float ri = rsqrtf(vx * vx + vy * vy + vz * vz + 1e-9f);
        float y0 = vx * ri, y1 = vy * ri, y2 = vz * ri;
        float* p = &g_f1[d * 192];
#pragma unroll
        for (int j = 0; j < 4; j++) {
            float v = INV * acc[i][j];
            int base = (c4 + j) * 3;
            atomicAdd(p + base + 0, v * y0);
            atomicAdd(p + base + 1, v * y1);
            atomicAdd(p + base + 2, v * y2);
        }
    }

    // --- GEMM5: Wattn (5 chunks of 64) -> fp16 store ---
    for (int ch = 0; ch < 5; ch++) {
        gemm_acc(SC, eA, Wattn, 320, ch * 64, cg, 64, acc);
        int col = ch * 64 + c4;
        float bx = battn[col], by = battn[col + 1], bz = battn[col + 2], bw = battn[col + 3];
#pragma unroll
        for (int i = 0; i < 4; i++) {
            long long wb = (long long)(ebase + eA + i) * 320 + col;
            __half2 p0 = __floats2half2_rn(acc[i][0] + bx, acc[i][1] + by);
            __half2 p1 = __floats2half2_rn(acc[i][2] + bz, acc[i][3] + bw);
            *reinterpret_cast<__half2*>(&g_wattn_h[wb]) = p0;
            *reinterpret_cast<__half2*>(&g_wattn_h[wb + 2]) = p1;
        }
    }
}

// ---------------- K2: messages + logits + segment max ----------------
__global__ void __launch_bounds__(256) k2_msg(
    const float* __restrict__ pos, const float* __restrict__ alpha_dot,
    const int* __restrict__ esrc, const int* __restrict__ edst)
{
    int warp = threadIdx.x >> 5, lane = threadIdx.x & 31;
    int e = blockIdx.x * 8 + warp;
    if (e >= NE) return;
    int s = esrc[e], d = edst[e];
    float vx = pos[d * 3 + 0] - pos[s * 3 + 0];
    float vy = pos[d * 3 + 1] - pos[s * 3 + 1];
    float vz = pos[d * 3 + 2] - pos[s * 3 + 2];
    float ri = rsqrtf(vx * vx + vy * vy + vz * vz + 1e-9f);
    float y0 = vx * ri, y1 = vy * ri, y2 = vz * ri;

    int c0 = lane, c1 = lane + 32;
    float s0a = g_f0[s * 64 + c0], s0b = g_f0[s * 64 + c1];
    const float* f1p = &g_f1[s * 192];
    float sa0 = f1p[c0 * 3], sa1 = f1p[c0 * 3 + 1], sa2 = f1p[c0 * 3 + 2];
    float sb0 = f1p[c1 * 3], sb1 = f1p[c1 * 3 + 1], sb2 = f1p[c1 * 3 + 2];

    long long wb = (long long)e * 320;
    float w0a = __half2float(g_wattn_h[wb + c0]),       w0b = __half2float(g_wattn_h[wb + c1]);
    float w1a = __half2float(g_wattn_h[wb + 64 + c0]),  w1b = __half2float(g_wattn_h[wb + 64 + c1]);
    float w2a = __half2float(g_wattn_h[wb + 128 + c0]), w2b = __half2float(g_wattn_h[wb + 128 + c1]);
    float w3a = __half2float(g_wattn_h[wb + 192 + c0]), w3b = __half2float(g_wattn_h[wb + 192 + c1]);
    float w4a = __half2float(g_wattn_h[wb + 256 + c0]), w4b = __half2float(g_wattn_h[wb + 256 + c1]);

    const float IS3 = 0.57735026918962576f;
    const float IS2 = 0.70710678118654752f;

    float dva = sa0 * y0 + sa1 * y1 + sa2 * y2;
    float dvb = sb0 * y0 + sb1 * y1 + sb2 * y2;
    float m0a = w0a * s0a + w3a * dva * IS3;
    float m0b = w0b * s0b + w3b * dvb * IS3;

    float cxa0 = sa1 * y2 - sa2 * y1, cxa1 = sa2 * y0 - sa0 * y2, cxa2 = sa0 * y1 - sa1 * y0;
    float cxb0 = sb1 * y2 - sb2 * y1, cxb1 = sb2 * y0 - sb0 * y2, cxb2 = sb0 * y1 - sb1 * y0;
    float w1sa = w1a * s0a, w1sb = w1b * s0b;
    float m1a0 = w1sa * y0 + w2a * sa0 + w4a * cxa0 * IS2;
    float m1a1 = w1sa * y1 + w2a * sa1 + w4a * cxa1 * IS2;
    float m1a2 = w1sa * y2 + w2a * sa2 + w4a * cxa2 * IS2;
    float m1b0 = w1sb * y0 + w2b * sb0 + w4b * cxb0 * IS2;
    float m1b1 = w1sb * y1 + w2b * sb1 + w4b * cxb1 * IS2;
    float m1b2 = w1sb * y2 + w2b * sb2 + w4b * cxb2 * IS2;

    long long mb0 = (long long)e * 64, mb1 = (long long)e * 192;
    g_msg0_h[mb0 + c0] = __float2half(m0a);
    g_msg0_h[mb0 + c1] = __float2half(m0b);
    g_msg1_h[mb1 + 0 * 64 + c0] = __float2half(m1a0);
    g_msg1_h[mb1 + 1 * 64 + c0] = __float2half(m1a1);
    g_msg1_h[mb1 + 2 * 64 + c0] = __float2half(m1a2);
    g_msg1_h[mb1 + 0 * 64 + c1] = __float2half(m1b0);
    g_msg1_h[mb1 + 1 * 64 + c1] = __float2half(m1b1);
    g_msg1_h[mb1 + 2 * 64 + c1] = __float2half(m1b2);

    float slra = 0.2f * m0a + 0.8f * m0a * sigf(m0a);
    float slrb = 0.2f * m0b + 0.8f * m0b * sigf(m0b);
    float pa = slra * alpha_dot[c0];
    float pb = slrb * alpha_dot[c1];
#pragma unroll
    for (int off = 4; off; off >>= 1) {
        pa += __shfl_xor_sync(0xffffffffu, pa, off);
        pb += __shfl_xor_sync(0xffffffffu, pb, off);
    }
    if ((lane & 7) == 0) {
        int h0 = lane >> 3;
        g_a[(long long)e * 8 + h0] = pa;
        g_a[(long long)e * 8 + h0 + 4] = pb;
        atomicMax(&g_amax[d * 8 + h0], encf(pa));
        atomicMax(&g_amax[d * 8 + h0 + 4], encf(pb));
    }
}

// ---------------- K3: exp + fused (z, ea*msg) scatter ----------------
__global__ void __launch_bounds__(256) k3_agg(const int* __restrict__ edst) {
    int warp = threadIdx.x >> 5, lane = threadIdx.x & 31;
    int e = blockIdx.x * 8 + warp;
    if (e >= NE) return;
    int d = edst[e];
    int h0 = lane >> 3, h1 = 4 + (lane >> 3);
    float aa = g_a[(long long)e * 8 + h0];
    float ab = g_a[(long long)e * 8 + h1];
    float ma = decf(g_amax[d * 8 + h0]);
    float mb = decf(g_amax[d * 8 + h1]);
    float eaa = expf(aa - ma), eab = expf(ab - mb);
    if ((lane & 7) == 0) {
        atomicAdd(&g_z[d * 8 + h0], eaa);
        atomicAdd(&g_z[d * 8 + h1], eab);
    }
    long long mb0 = (long long)e * 64, mb1 = (long long)e * 192;
    int c0 = lane, c1 = lane + 32;
    atomicAdd(&g_agg0[d * 64 + c0], eaa * __half2float(g_msg0_h[mb0 + c0]));
    atomicAdd(&g_agg0[d * 64 + c1], eab * __half2float(g_msg0_h[mb0 + c1]));
#pragma unroll
    for (int i = 0; i < 3; i++) {
        atomicAdd(&g_agg1[d * 192 + c0 * 3 + i], eaa * __half2float(g_msg1_h[mb1 + i * 64 + c0]));
        atomicAdd(&g_agg1[d * 192 + c1 * 3 + i], eab * __half2float(g_msg1_h[mb1 + i * 64 + c1]));
    }
}

// ---------------- K4: node update: out-proj + FFN + write output ----------------
__global__ void __launch_bounds__(256) k4_node(
    const float* __restrict__ P0, const float* __restrict__ P1,
    const float* __restrict__ W1s, const float* __restrict__ b1s,
    const float* __restrict__ W1v, const float* __restrict__ W2s,
    const float* __restrict__ b2s, const float* __restrict__ W2v,
    float* __restrict__ out)
{
    __shared__ float sm[8][832];
    int warp = threadIdx.x >> 5, lane = threadIdx.x & 31;
    int n = blockIdx.x * 8 + warp;
    if (n >= NN) return;
    float* sA0 = sm[warp];
    float* sA1 = sm[warp] + 64;
    float* sF0 = sm[warp] + 256;
    float* sF1 = sm[warp] + 320;
    float* sMS = sm[warp] + 512;
    float* sG  = sm[warp] + 576;
    float* sMV = sm[warp] + 640;

    int c0 = lane, c1 = lane + 32;
    float za = g_z[n * 8 + (lane >> 3)];
    float zb = g_z[n * 8 + 4 + (lane >> 3)];
    float rza = za > 0.f ? 1.f / za : 0.f;
    float rzb = zb > 0.f ? 1.f / zb : 0.f;
    sA0[c0] = g_agg0[n * 64 + c0] * rza;
    sA0[c1] = g_agg0[n * 64 + c1] * rzb;
#pragma unroll
    for (int i = 0; i < 3; i++) {
        sA1[c0 * 3 + i] = g_agg1[n * 192 + c0 * 3 + i] * rza;
        sA1[c1 * 3 + i] = g_agg1[n * 192 + c1 * 3 + i] * rzb;
    }
    sF0[c0] = g_f0[n * 64 + c0];
    sF0[c1] = g_f0[n * 64 + c1];
#pragma unroll
    for (int i = 0; i < 3; i++) {
        sF1[c0 * 3 + i] = g_f1[n * 192 + c0 * 3 + i];
        sF1[c1 * 3 + i] = g_f1[n * 192 + c1 * 3 + i];
    }
    __syncwarp();

    float f0a = sF0[c0], f0b = sF0[c1];
    float f1a[3] = {sF1[c0 * 3], sF1[c0 * 3 + 1], sF1[c0 * 3 + 2]};
    float f1b[3] = {sF1[c1 * 3], sF1[c1 * 3 + 1], sF1[c1 * 3 + 2]};
#pragma unroll 4
    for (int c = 0; c < 64; c++) {
        float r = sA0[c];
        f0a += r * P0[c * 64 + c0];
        f0b += r * P0[c * 64 + c1];
        float wa = P1[c * 64 + c0], wbv = P1[c * 64 + c1];
#pragma unroll
        for (int i = 0; i < 3; i++) {
            f1a[i] += sA1[c * 3 + i] * wa;
            f1b[i] += sA1[c * 3 + i] * wbv;
        }
    }
    __syncwarp();
    sF0[c0] = f0a; sF0[c1] = f0b;
#pragma unroll
    for (int i = 0; i < 3; i++) { sF1[c0 * 3 + i] = f1a[i]; sF1[c1 * 3 + i] = f1b[i]; }
    __syncwarp();

    float hs0 = b1s[c0], hs1 = b1s[c1], hs2 = b1s[64 + c0], hs3 = b1s[64 + c1];
#pragma unroll 4
    for (int c = 0; c < 64; c++) {
        float r = sF0[c];
        hs0 += r * W1s[c * 128 + c0];
        hs1 += r * W1s[c * 128 + c1];
        hs2 += r * W1s[c * 128 + 64 + c0];
        hs3 += r * W1s[c * 128 + 64 + c1];
    }
    sMS[c0] = siluf(hs0); sMS[c1] = siluf(hs1);
    sG[c0] = sigf(hs2);   sG[c1] = sigf(hs3);
    __syncwarp();

    float mva[3] = {0, 0, 0}, mvb[3] = {0, 0, 0};
#pragma unroll 4
    for (int c = 0; c < 64; c++) {
        float wa = W1v[c * 64 + c0], wbv = W1v[c * 64 + c1];
#pragma unroll
        for (int i = 0; i < 3; i++) {
            mva[i] += sF1[c * 3 + i] * wa;
            mvb[i] += sF1[c * 3 + i] * wbv;
        }
    }
    float ga = sG[c0], gb = sG[c1];
#pragma unroll
    for (int i = 0; i < 3; i++) { sMV[c0 * 3 + i] = mva[i] * ga; sMV[c1 * 3 + i] = mvb[i] * gb; }
    __syncwarp();

    float o0a = sF0[c0] + b2s[c0], o0b = sF0[c1] + b2s[c1];
    float o1a[3] = {sF1[c0 * 3], sF1[c0 * 3 + 1], sF1[c0 * 3 + 2]};
    float o1b[3] = {sF1[c1 * 3], sF1[c1 * 3 + 1], sF1[c1 * 3 + 2]};
#pragma unroll 4
    for (int c = 0; c < 64; c++) {
        float r = sMS[c];
        o0a += r * W2s[c * 64 + c0];
        o0b += r * W2s[c * 64 + c1];
        float wa = W2v[c * 64 + c0], wbv = W2v[c * 64 + c1];
#pragma unroll
        for (int i = 0; i < 3; i++) {
            o1a[i] += sMV[c * 3 + i] * wa;
            o1b[i] += sMV[c * 3 + i] * wbv;
        }
    }

    long long ob = (long long)n * 256;
    out[ob + c0] = o0a;
    out[ob + c1] = o0b;
#pragma unroll
    for (int i = 0; i < 3; i++) {
        out[ob + 64 + c0 * 3 + i] = o1a[i];
        out[ob + 64 + c1 * 3 + i] = o1b[i];
    }
}

// ---------------- launch ----------------
extern "C" void kernel_launch(void* const* d_in, const int* in_sizes, int n_in,
                              void* d_out, int out_size) {
    const float* pos       = (const float*)d_in[0];
    const float* embed_W   = (const float*)d_in[1];
    const float* exp_w     = (const float*)d_in[2];
    const float* rad_W1    = (const float*)d_in[3];
    const float* rad_b1    = (const float*)d_in[4];
    const float* rad_W2    = (const float*)d_in[5];
    const float* rad_b2    = (const float*)d_in[6];
    const float* rad_Wdeg  = (const float*)d_in[7];
    const float* rad_bdeg  = (const float*)d_in[8];
    const float* rad_Wattn = (const float*)d_in[9];
    const float* rad_battn = (const float*)d_in[10];
    const float* deg_proj0 = (const float*)d_in[11];
    const float* deg_proj1 = (const float*)d_in[12];
    const float* alpha_dot = (const float*)d_in[13];
    const float* out_proj0 = (const float*)d_in[14];
    const float* out_proj1 = (const float*)d_in[15];
    const float* ffn_W1s   = (const float*)d_in[16];
    const float* ffn_b1s   = (const float*)d_in[17];
    const float* ffn_W1v   = (const float*)d_in[18];
    const float* ffn_W2s   = (const float*)d_in[19];
    const float* ffn_b2s   = (const float*)d_in[20];
    const float* ffn_W2v   = (const float*)d_in[21];
    const int* node_atom   = (const int*)d_in[22];
    const int* edge_src    = (const int*)d_in[23];
    const int* edge_dst    = (const int*)d_in[24];
    float* out = (float*)d_out;

    k0_init<<<1024, 256>>>(embed_W, node_atom);
    k1_edge<<<NE / 64, 256>>>(pos, exp_w, rad_W1, rad_b1, rad_W2, rad_b2,
                              rad_Wdeg, rad_bdeg, rad_Wattn, rad_battn,
                              deg_proj0, deg_proj1, edge_src, edge_dst);
    k2_msg<<<NE / 8, 256>>>(pos, alpha_dot, edge_src, edge_dst);
    k3_agg<<<NE / 8, 256>>>(edge_dst);
    k4_node<<<NN / 8, 256>>>(out_proj0, out_proj1, ffn_W1s, ffn_b1s,
                             ffn_W1v, ffn_W2s, ffn_b2s, ffn_W2v, out);
}

// round 4
// speedup vs baseline: 2.2987x; 1.1517x over previous
#include <cuda_runtime.h>
#include <cuda_fp16.h>
#include <math.h>

#define NN 50000
#define NE 800000
#define LDS_S 66

// ---------------- scratch (device globals; no allocation allowed) ----------------
__device__ float g_f0[NN * 64];
__device__ float g_f1[NN * 192];
__device__ float g_agg0[NN * 64];
__device__ float g_agg1[NN * 192];
__device__ float g_z[NN * 8];
__device__ unsigned int g_amax[NN * 8];
__device__ __half g_wattn_h[256000000];    // E*320 (fp16)
__device__ __half g_msg0_h[51200000];      // E*64
__device__ __half g_msg1_h[153600000];     // E*192, layout [e][comp][64]
__device__ float g_a[6400000];             // E*8

typedef unsigned long long u64;

// ---------------- helpers ----------------
__device__ __forceinline__ float siluf(float x) { return x / (1.f + expf(-x)); }
__device__ __forceinline__ float sigf(float x) { return 1.f / (1.f + expf(-x)); }

__device__ __forceinline__ unsigned int encf(float f) {
    unsigned int u = __float_as_uint(f);
    return (u & 0x80000000u) ? ~u : (u | 0x80000000u);
}
__device__ __forceinline__ float decf(unsigned int u) {
    return (u & 0x80000000u) ? __uint_as_float(u ^ 0x80000000u) : __uint_as_float(~u);
}

// packed f32x2 ops
__device__ __forceinline__ u64 pk(float x) {
    u64 r; asm("mov.b64 %0, {%1, %1};" : "=l"(r) : "f"(x)); return r;
}
__device__ __forceinline__ void fma2(u64& d, u64 a, u64 b) {
    asm("fma.rn.f32x2 %0, %1, %2, %0;" : "+l"(d) : "l"(a), "l"(b));
}
__device__ __forceinline__ float2 up(u64 a) {
    float2 v; asm("mov.b64 {%0, %1}, %2;" : "=f"(v.x), "=f"(v.y) : "l"(a)); return v;
}

// ---------------- K0: init node state ----------------
__global__ void k0_init(const float* __restrict__ embed_W, const int* __restrict__ node_atom) {
    int stride = gridDim.x * blockDim.x;
    for (int i = blockIdx.x * blockDim.x + threadIdx.x; i < NN * 192; i += stride) {
        g_f1[i] = 0.f;
        g_agg1[i] = 0.f;
        if (i < NN * 64) {
            int n = i >> 6, c = i & 63;
            g_f0[i] = embed_W[node_atom[n] * 64 + c];
            g_agg0[i] = 0.f;
        }
        if (i < NN * 8) {
            g_amax[i] = 0x007FFFFFu;
            g_z[i] = 0.f;
        }
    }
}

// ---------------- k-major GEMM core with f32x2 ----------------
// As: smem [K][64 edges] (stride LDS_S). Thread: edges eA..eA+7 (4 pairs), cols c4..c4+3.
__device__ __forceinline__ void gemm_t(const float* __restrict__ As, int eA,
                                       const float* __restrict__ Bg, int ldb,
                                       int colbase, int c4, int K,
                                       u64 acc[4][4]) {
#pragma unroll
    for (int p = 0; p < 4; p++)
#pragma unroll
        for (int j = 0; j < 4; j++) acc[p][j] = 0ull;
    const float* Bp = Bg + colbase + c4;
#pragma unroll 4
    for (int k = 0; k < K; k++) {
        const u64* ap = reinterpret_cast<const u64*>(As + k * LDS_S + eA);
        u64 a0 = ap[0], a1 = ap[1], a2 = ap[2], a3 = ap[3];
        float4 b = *reinterpret_cast<const float4*>(Bp + k * ldb);
        u64 bx = pk(b.x), by = pk(b.y), bz = pk(b.z), bw = pk(b.w);
        fma2(acc[0][0], a0, bx); fma2(acc[0][1], a0, by); fma2(acc[0][2], a0, bz); fma2(acc[0][3], a0, bw);
        fma2(acc[1][0], a1, bx); fma2(acc[1][1], a1, by); fma2(acc[1][2], a1, bz); fma2(acc[1][3], a1, bw);
        fma2(acc[2][0], a2, bx); fma2(acc[2][1], a2, by); fma2(acc[2][2], a2, bz); fma2(acc[2][3], a2, bw);
        fma2(acc[3][0], a3, bx); fma2(acc[3][1], a3, by); fma2(acc[3][2], a3, bz); fma2(acc[3][3], a3, bw);
    }
}

// ---------------- K1: edge-tiled radial MLP + degree scatter + w_attn ----------------
__global__ void __launch_bounds__(128) k1_edge(
    const float* __restrict__ pos, const float* __restrict__ exp_w,
    const float* __restrict__ W1, const float* __restrict__ b1,
    const float* __restrict__ W2, const float* __restrict__ b2,
    const float* __restrict__ Wdeg, const float* __restrict__ bdeg,
    const float* __restrict__ Wattn, const float* __restrict__ battn,
    const float* __restrict__ P0, const float* __restrict__ P1,
    const int* __restrict__ esrc, const int* __restrict__ edst)
{
    __shared__ float SA[64 * LDS_S];
    __shared__ float SB[64 * LDS_S];
    __shared__ float sy[3][64];
    __shared__ int sdst[64];
    __shared__ float stmp[2][64];

    int tid = threadIdx.x;
    int cg = tid & 15, c4 = cg << 2;
    int eg = tid >> 4, eA = eg << 3;       // 8 edges per thread, 8 groups
    int ebase = blockIdx.x * 64;

    // geometry (threads 0..63, one edge each)
    if (tid < 64) {
        int e = ebase + tid;
        int s = esrc[e], d = edst[e];
        float vx = pos[d * 3 + 0] - pos[s * 3 + 0];
        float vy = pos[d * 3 + 1] - pos[s * 3 + 1];
        float vz = pos[d * 3 + 2] - pos[s * 3 + 2];
        float dist = sqrtf(vx * vx + vy * vy + vz * vz + 1e-9f);
        float ri = 1.f / dist;
        const float PI_ = 3.14159265358979323846f;
        float cut = (dist < 5.0f) ? 0.5f * (cosf(PI_ * dist * 0.2f) + 1.f) : 0.f;
        sdst[tid] = d;
        sy[0][tid] = vx * ri; sy[1][tid] = vy * ri; sy[2][tid] = vz * ri;
        stmp[0][tid] = cut;
        stmp[1][tid] = expf(-dist);
    }
    __syncthreads();

    // RBF into SA[k][e]
    {
        const float START = 0.006737946999085467f;
        const float STEP = (1.0f - START) / 49.0f;
        const float BETA = 1.0f / ((0.04f * (1.0f - START)) * (0.04f * (1.0f - START)));
        int er = tid & 63, k0 = tid >> 6;   // k0 in 0..1
        float cut = stmp[0][er], expd = stmp[1][er];
        for (int k = k0; k < 50; k += 2) {
            float t = expd - (START + (float)k * STEP);
            SA[k * LDS_S + er] = cut * expf(-BETA * t * t);
        }
    }
    __syncthreads();

    u64 acc[4][4];

    // GEMM1: rbf(50) -> 64, silu -> SB (transposed)
    gemm_t(SA, eA, W1, 64, 0, c4, 50, acc);
    {
#pragma unroll
        for (int j = 0; j < 4; j++) {
            float bb = b1[c4 + j];
#pragma unroll
            for (int p = 0; p < 4; p++) {
                float2 v = up(acc[p][j]);
                v.x = siluf(v.x + bb); v.y = siluf(v.y + bb);
                *reinterpret_cast<float2*>(&SB[(c4 + j) * LDS_S + eA + 2 * p]) = v;
            }
        }
    }
    __syncthreads();

    // GEMM2: 64 -> 64, silu -> SA (h2)
    gemm_t(SB, eA, W2, 64, 0, c4, 64, acc);
    {
#pragma unroll
        for (int j = 0; j < 4; j++) {
            float bb = b2[c4 + j];
#pragma unroll
            for (int p = 0; p < 4; p++) {
                float2 v = up(acc[p][j]);
                v.x = siluf(v.x + bb); v.y = siluf(v.y + bb);
                *reinterpret_cast<float2*>(&SA[(c4 + j) * LDS_S + eA + 2 * p]) = v;
            }
        }
    }
    __syncthreads();

    // GEMM5: w_attn = h2 @ Wattn (5 chunks of 64) -> fp16 global
    for (int ch = 0; ch < 5; ch++) {
        gemm_t(SA, eA, Wattn, 320, ch * 64, c4, 64, acc);
        int col = ch * 64 + c4;
        float b0v = battn[col], b1v = battn[col + 1], b2v = battn[col + 2], b3v = battn[col + 3];
#pragma unroll
        for (int p = 0; p < 4; p++) {
            float2 v0 = up(acc[p][0]), v1 = up(acc[p][1]), v2 = up(acc[p][2]), v3 = up(acc[p][3]);
            long long wbA = (long long)(ebase + eA + 2 * p) * 320 + col;
            long long wbB = wbA + 320;
            *reinterpret_cast<__half2*>(&g_wattn_h[wbA])     = __floats2half2_rn(v0.x + b0v, v1.x + b1v);
            *reinterpret_cast<__half2*>(&g_wattn_h[wbA + 2]) = __floats2half2_rn(v2.x + b2v, v3.x + b3v);
            *reinterpret_cast<__half2*>(&g_wattn_h[wbB])     = __floats2half2_rn(v0.y + b0v, v1.y + b1v);
            *reinterpret_cast<__half2*>(&g_wattn_h[wbB + 2]) = __floats2half2_rn(v2.y + b2v, v3.y + b3v);
        }
    }

    const float INV = 0.25f;  // 1/sqrt(AVG_DEG)

    // GEMM3a: e0 = (h2 @ Wdeg[:, :64] + b)*exp_w -> SB
    gemm_t(SA, eA, Wdeg, 128, 0, c4, 64, acc);
    {
#pragma unroll
        for (int j = 0; j < 4; j++) {
            float bb = bdeg[c4 + j], ee = exp_w[c4 + j];
#pragma unroll
            for (int p = 0; p < 4; p++) {
                float2 v = up(acc[p][j]);
                v.x = (v.x + bb) * ee; v.y = (v.y + bb) * ee;
                *reinterpret_cast<float2*>(&SB[(c4 + j) * LDS_S + eA + 2 * p]) = v;
            }
        }
    }
    __syncthreads();

    // GEMM4a: e0 @ P0 -> atomic scatter to f0
    gemm_t(SB, eA, P0, 64, 0, c4, 64, acc);
#pragma unroll
    for (int p = 0; p < 4; p++) {
        int dA = sdst[eA + 2 * p], dB = sdst[eA + 2 * p + 1];
        float2 v0 = up(acc[p][0]), v1 = up(acc[p][1]), v2 = up(acc[p][2]), v3 = up(acc[p][3]);
        float* pa = &g_f0[dA * 64 + c4];
        float* pb = &g_f0[dB * 64 + c4];
        atomicAdd(pa + 0, INV * v0.x); atomicAdd(pa + 1, INV * v1.x);
        atomicAdd(pa + 2, INV * v2.x); atomicAdd(pa + 3, INV * v3.x);
        atomicAdd(pb + 0, INV * v0.y); atomicAdd(pb + 1, INV * v1.y);
        atomicAdd(pb + 2, INV * v2.y); atomicAdd(pb + 3, INV * v3.y);
    }
    __syncthreads();

    // GEMM3b: e1 = (h2 @ Wdeg[:, 64:] + b)*exp_w -> SB
    gemm_t(SA, eA, Wdeg, 128, 64, c4, 64, acc);
    {
#pragma unroll
        for (int j = 0; j < 4; j++) {
            float bb = bdeg[64 + c4 + j], ee = exp_w[c4 + j];
#pragma unroll
            for (int p = 0; p < 4; p++) {
                float2 v = up(acc[p][j]);
                v.x = (v.x + bb) * ee; v.y = (v.y + bb) * ee;
                *reinterpret_cast<float2*>(&SB[(c4 + j) * LDS_S + eA + 2 * p]) = v;
            }
        }
    }
    __syncthreads();

    // GEMM4b: e1 @ P1, times Y -> atomic scatter to f1
    gemm_t(SB, eA, P1, 64, 0, c4, 64, acc);
#pragma unroll
    for (int p = 0; p < 4; p++) {
#pragma unroll
        for (int half = 0; half < 2; half++) {
            int el = eA + 2 * p + half;
            int d = sdst[el];
            float y0 = sy[0][el], y1 = sy[1][el], y2 = sy[2][el];
            float* pp = &g_f1[d * 192];
#pragma unroll
            for (int j = 0; j < 4; j++) {
                float2 v = up(acc[p][j]);
                float val = INV * (half ? v.y : v.x);
                int base = (c4 + j) * 3;
                atomicAdd(pp + base + 0, val * y0);
                atomicAdd(pp + base + 1, val * y1);
                atomicAdd(pp + base + 2, val * y2);
            }
        }
    }
}

// ---------------- K2: messages + logits + segment max ----------------
__global__ void __launch_bounds__(256) k2_msg(
    const float* __restrict__ pos, const float* __restrict__ alpha_dot,
    const int* __restrict__ esrc, const int* __restrict__ edst)
{
    int warp = threadIdx.x >> 5, lane = threadIdx.x & 31;
    int e = blockIdx.x * 8 + warp;
    if (e >= NE) return;
    int s = esrc[e], d = edst[e];
    float vx = pos[d * 3 + 0] - pos[s * 3 + 0];
    float vy = pos[d * 3 + 1] - pos[s * 3 + 1];
    float vz = pos[d * 3 + 2] - pos[s * 3 + 2];
    float ri = rsqrtf(vx * vx + vy * vy + vz * vz + 1e-9f);
    float y0 = vx * ri, y1 = vy * ri, y2 = vz * ri;

    int c0 = lane, c1 = lane + 32;
    float s0a = g_f0[s * 64 + c0], s0b = g_f0[s * 64 + c1];
    const float* f1p = &g_f1[s * 192];
    float sa0 = f1p[c0 * 3], sa1 = f1p[c0 * 3 + 1], sa2 = f1p[c0 * 3 + 2];
    float sb0 = f1p[c1 * 3], sb1 = f1p[c1 * 3 + 1], sb2 = f1p[c1 * 3 + 2];

    long long wb = (long long)e * 320;
    float w0a = __half2float(g_wattn_h[wb + c0]),       w0b = __half2float(g_wattn_h[wb + c1]);
    float w1a = __half2float(g_wattn_h[wb + 64 + c0]),  w1b = __half2float(g_wattn_h[wb + 64 + c1]);
    float w2a = __half2float(g_wattn_h[wb + 128 + c0]), w2b = __half2float(g_wattn_h[wb + 128 + c1]);
    float w3a = __half2float(g_wattn_h[wb + 192 + c0]), w3b = __half2float(g_wattn_h[wb + 192 + c1]);
    float w4a = __half2float(g_wattn_h[wb + 256 + c0]), w4b = __half2float(g_wattn_h[wb + 256 + c1]);

    const float IS3 = 0.57735026918962576f;
    const float IS2 = 0.70710678118654752f;

    float dva = sa0 * y0 + sa1 * y1 + sa2 * y2;
    float dvb = sb0 * y0 + sb1 * y1 + sb2 * y2;
    float m0a = w0a * s0a + w3a * dva * IS3;
    float m0b = w0b * s0b + w3b * dvb * IS3;

    float cxa0 = sa1 * y2 - sa2 * y1, cxa1 = sa2 * y0 - sa0 * y2, cxa2 = sa0 * y1 - sa1 * y0;
    float cxb0 = sb1 * y2 - sb2 * y1, cxb1 = sb2 * y0 - sb0 * y2, cxb2 = sb0 * y1 - sb1 * y0;
    float w1sa = w1a * s0a, w1sb = w1b * s0b;
    float m1a0 = w1sa * y0 + w2a * sa0 + w4a * cxa0 * IS2;
    float m1a1 = w1sa * y1 + w2a * sa1 + w4a * cxa1 * IS2;
    float m1a2 = w1sa * y2 + w2a * sa2 + w4a * cxa2 * IS2;
    float m1b0 = w1sb * y0 + w2b * sb0 + w4b * cxb0 * IS2;
    float m1b1 = w1sb * y1 + w2b * sb1 + w4b * cxb1 * IS2;
    float m1b2 = w1sb * y2 + w2b * sb2 + w4b * cxb2 * IS2;

    long long mb0 = (long long)e * 64, mb1 = (long long)e * 192;
    g_msg0_h[mb0 + c0] = __float2half(m0a);
    g_msg0_h[mb0 + c1] = __float2half(m0b);
    g_msg1_h[mb1 + 0 * 64 + c0] = __float2half(m1a0);
    g_msg1_h[mb1 + 1 * 64 + c0] = __float2half(m1a1);
    g_msg1_h[mb1 + 2 * 64 + c0] = __float2half(m1a2);
    g_msg1_h[mb1 + 0 * 64 + c1] = __float2half(m1b0);
    g_msg1_h[mb1 + 1 * 64 + c1] = __float2half(m1b1);
    g_msg1_h[mb1 + 2 * 64 + c1] = __float2half(m1b2);

    float slra = 0.2f * m0a + 0.8f * m0a * sigf(m0a);
    float slrb = 0.2f * m0b + 0.8f * m0b * sigf(m0b);
    float pa = slra * alpha_dot[c0];
    float pb = slrb * alpha_dot[c1];
#pragma unroll
    for (int off = 4; off; off >>= 1) {
        pa += __shfl_xor_sync(0xffffffffu, pa, off);
        pb += __shfl_xor_sync(0xffffffffu, pb, off);
    }
    if ((lane & 7) == 0) {
        int h0 = lane >> 3;
        g_a[(long long)e * 8 + h0] = pa;
        g_a[(long long)e * 8 + h0 + 4] = pb;
        atomicMax(&g_amax[d * 8 + h0], encf(pa));
        atomicMax(&g_amax[d * 8 + h0 + 4], encf(pb));
    }
}

// ---------------- K3: exp + fused (z, ea*msg) scatter ----------------
__global__ void __launch_bounds__(256) k3_agg(const int* __restrict__ edst) {
    int warp = threadIdx.x >> 5, lane = threadIdx.x & 31;
    int e = blockIdx.x * 8 + warp;
    if (e >= NE) return;
    int d = edst[e];
    int h0 = lane >> 3, h1 = 4 + (lane >> 3);
    float aa = g_a[(long long)e * 8 + h0];
    float ab = g_a[(long long)e * 8 + h1];
    float ma = decf(g_amax[d * 8 + h0]);
    float mb = decf(g_amax[d * 8 + h1]);
    float eaa = expf(aa - ma), eab = expf(ab - mb);
    if ((lane & 7) == 0) {
        atomicAdd(&g_z[d * 8 + h0], eaa);
        atomicAdd(&g_z[d * 8 + h1], eab);
    }
    long long mb0 = (long long)e * 64, mb1 = (long long)e * 192;
    int c0 = lane, c1 = lane + 32;
    atomicAdd(&g_agg0[d * 64 + c0], eaa * __half2float(g_msg0_h[mb0 + c0]));
    atomicAdd(&g_agg0[d * 64 + c1], eab * __half2float(g_msg0_h[mb0 + c1]));
#pragma unroll
    for (int i = 0; i < 3; i++) {
        atomicAdd(&g_agg1[d * 192 + c0 * 3 + i], eaa * __half2float(g_msg1_h[mb1 + i * 64 + c0]));
        atomicAdd(&g_agg1[d * 192 + c1 * 3 + i], eab * __half2float(g_msg1_h[mb1 + i * 64 + c1]));
    }
}

// ---------------- K4: node update ----------------
__global__ void __launch_bounds__(256) k4_node(
    const float* __restrict__ P0, const float* __restrict__ P1,
    const float* __restrict__ W1s, const float* __restrict__ b1s,
    const float* __restrict__ W1v, const float* __restrict__ W2s,
    const float* __restrict__ b2s, const float* __restrict__ W2v,
    float* __restrict__ out)
{
    __shared__ float sm[8][832];
    int warp = threadIdx.x >> 5, lane = threadIdx.x & 31;
    int n = blockIdx.x * 8 + warp;
    if (n >= NN) return;
    float* sA0 = sm[warp];
    float* sA1 = sm[warp] + 64;
    float* sF0 = sm[warp] + 256;
    float* sF1 = sm[warp] + 320;
    float* sMS = sm[warp] + 512;
    float* sG  = sm[warp] + 576;
    float* sMV = sm[warp] + 640;

    int c0 = lane, c1 = lane + 32;
    float za = g_z[n * 8 + (lane >> 3)];
    float zb = g_z[n * 8 + 4 + (lane >> 3)];
    float rza = za > 0.f ? 1.f / za : 0.f;
    float rzb = zb > 0.f ? 1.f / zb : 0.f;
    sA0[c0] = g_agg0[n * 64 + c0] * rza;
    sA0[c1] = g_agg0[n * 64 + c1] * rzb;
#pragma unroll
    for (int i = 0; i < 3; i++) {
        sA1[c0 * 3 + i] = g_agg1[n * 192 + c0 * 3 + i] * rza;
        sA1[c1 * 3 + i] = g_agg1[n * 192 + c1 * 3 + i] * rzb;
    }
    sF0[c0] = g_f0[n * 64 + c0];
    sF0[c1] = g_f0[n * 64 + c1];
#pragma unroll
    for (int i = 0; i < 3; i++) {
        sF1[c0 * 3 + i] = g_f1[n * 192 + c0 * 3 + i];
        sF1[c1 * 3 + i] = g_f1[n * 192 + c1 * 3 + i];
    }
    __syncwarp();

    float f0a = sF0[c0], f0b = sF0[c1];
    float f1a[3] = {sF1[c0 * 3], sF1[c0 * 3 + 1], sF1[c0 * 3 + 2]};
    float f1b[3] = {sF1[c1 * 3], sF1[c1 * 3 + 1], sF1[c1 * 3 + 2]};
#pragma unroll 4
    for (int c = 0; c < 64; c++) {
        float r = sA0[c];
        f0a += r * P0[c * 64 + c0];
        f0b += r * P0[c * 64 + c1];
        float wa = P1[c * 64 + c0], wbv = P1[c * 64 + c1];
#pragma unroll
        for (int i = 0; i < 3; i++) {
            f1a[i] += sA1[c * 3 + i] * wa;
            f1b[i] += sA1[c * 3 + i] * wbv;
        }
    }
    __syncwarp();
    sF0[c0] = f0a; sF0[c1] = f0b;
#pragma unroll
    for (int i = 0; i < 3; i++) { sF1[c0 * 3 + i] = f1a[i]; sF1[c1 * 3 + i] = f1b[i]; }
    __syncwarp();

    float hs0 = b1s[c0], hs1 = b1s[c1], hs2 = b1s[64 + c0], hs3 = b1s[64 + c1];
#pragma unroll 4
    for (int c = 0; c < 64; c++) {
        float r = sF0[c];
        hs0 += r * W1s[c * 128 + c0];
        hs1 += r * W1s[c * 128 + c1];
        hs2 += r * W1s[c * 128 + 64 + c0];
        hs3 += r * W1s[c * 128 + 64 + c1];
    }
    sMS[c0] = siluf(hs0); sMS[c1] = siluf(hs1);
    sG[c0] = sigf(hs2);   sG[c1] = sigf(hs3);
    __syncwarp();

    float mva[3] = {0, 0, 0}, mvb[3] = {0, 0, 0};
#pragma unroll 4
    for (int c = 0; c < 64; c++) {
        float wa = W1v[c * 64 + c0], wbv = W1v[c * 64 + c1];
#pragma unroll
        for (int i = 0; i < 3; i++) {
            mva[i] += sF1[c * 3 + i] * wa;
            mvb[i] += sF1[c * 3 + i] * wbv;
        }
    }
    float ga = sG[c0], gb = sG[c1];
#pragma unroll
    for (int i = 0; i < 3; i++) { sMV[c0 * 3 + i] = mva[i] * ga; sMV[c1 * 3 + i] = mvb[i] * gb; }
    __syncwarp();

    float o0a = sF0[c0] + b2s[c0], o0b = sF0[c1] + b2s[c1];
    float o1a[3] = {sF1[c0 * 3], sF1[c0 * 3 + 1], sF1[c0 * 3 + 2]};
    float o1b[3] = {sF1[c1 * 3], sF1[c1 * 3 + 1], sF1[c1 * 3 + 2]};
#pragma unroll 4
    for (int c = 0; c < 64; c++) {
        float r = sMS[c];
        o0a += r * W2s[c * 64 + c0];
        o0b += r * W2s[c * 64 + c1];
        float wa = W2v[c * 64 + c0], wbv = W2v[c * 64 + c1];
#pragma unroll
        for (int i = 0; i < 3; i++) {
            o1a[i] += sMV[c * 3 + i] * wa;
            o1b[i] += sMV[c * 3 + i] * wbv;
        }
    }

    long long ob = (long long)n * 256;
    out[ob + c0] = o0a;
    out[ob + c1] = o0b;
#pragma unroll
    for (int i = 0; i < 3; i++) {
        out[ob + 64 + c0 * 3 + i] = o1a[i];
        out[ob + 64 + c1 * 3 + i] = o1b[i];
    }
}

// ---------------- launch ----------------
extern "C" void kernel_launch(void* const* d_in, const int* in_sizes, int n_in,
                              void* d_out, int out_size) {
    const float* pos       = (const float*)d_in[0];
    const float* embed_W   = (const float*)d_in[1];
    const float* exp_w     = (const float*)d_in[2];
    const float* rad_W1    = (const float*)d_in[3];
    const float* rad_b1    = (const float*)d_in[4];
    const float* rad_W2    = (const float*)d_in[5];
    const float* rad_b2    = (const float*)d_in[6];
    const float* rad_Wdeg  = (const float*)d_in[7];
    const float* rad_bdeg  = (const float*)d_in[8];
    const float* rad_Wattn = (const float*)d_in[9];
    const float* rad_battn = (const float*)d_in[10];
    const float* deg_proj0 = (const float*)d_in[11];
    const float* deg_proj1 = (const float*)d_in[12];
    const float* alpha_dot = (const float*)d_in[13];
    const float* out_proj0 = (const float*)d_in[14];
    const float* out_proj1 = (const float*)d_in[15];
    const float* ffn_W1s   = (const float*)d_in[16];
    const float* ffn_b1s   = (const float*)d_in[17];
    const float* ffn_W1v   = (const float*)d_in[18];
    const float* ffn_W2s   = (const float*)d_in[19];
    const float* ffn_b2s   = (const float*)d_in[20];
    const float* ffn_W2v   = (const float*)d_in[21];
    const int* node_atom   = (const int*)d_in[22];
    const int* edge_src    = (const int*)d_in[23];
    const int* edge_dst    = (const int*)d_in[24];
    float* out = (float*)d_out;

    k0_init<<<1024, 256>>>(embed_W, node_atom);
    k1_edge<<<NE / 64, 128>>>(pos, exp_w, rad_W1, rad_b1, rad_W2, rad_b2,
                              rad_Wdeg, rad_bdeg, rad_Wattn, rad_battn,
                              deg_proj0, deg_proj1, edge_src, edge_dst);
    k2_msg<<<NE / 8, 256>>>(pos, alpha_dot, edge_src, edge_dst);
    k3_agg<<<NE / 8, 256>>>(edge_dst);
    k4_node<<<NN / 8, 256>>>(out_proj0, out_proj1, ffn_W1s, ffn_b1s,
                             ffn_W1v, ffn_W2s, ffn_b2s, ffn_W2v, out);
}